// round 1
// baseline (speedup 1.0000x reference)
#include <cuda_runtime.h>

#define NB   50
#define HID  32
#define HALFD 16
#define JJ   16          // HID/2 packed pairs
#define VST  33          // padded V row stride (odd -> conflict-free banks)
#define TPB  256
#define RPT  8           // rows per thread

// Precomputed combined head weights (scratch: __device__ globals, no alloc)
__device__ float g_V[NB * VST];
__device__ float g_c[NB];

__global__ void precompute_kernel(const float* __restrict__ W2, const float* __restrict__ b2,
                                  const float* __restrict__ Wh, const float* __restrict__ bh) {
    int t  = blockIdx.x * blockDim.x + threadIdx.x;
    int nt = gridDim.x * blockDim.x;
    // V[b][j] = sum_k W2[j][k] * Wh[b][k]
    for (int e = t; e < NB * HID; e += nt) {
        int b = e >> 5, j = e & 31;
        float s = 0.f;
        #pragma unroll
        for (int k = 0; k < HALFD; k++)
            s = fmaf(W2[j * HALFD + k], Wh[b * HALFD + k], s);
        g_V[b * VST + j] = s;
    }
    // c[b] = bh[b] + sum_k b2[k] * Wh[b][k]
    for (int b = t; b < NB; b += nt) {
        float s = bh[b];
        #pragma unroll
        for (int k = 0; k < HALFD; k++)
            s = fmaf(b2[k], Wh[b * HALFD + k], s);
        g_c[b] = s;
    }
}

__device__ __forceinline__ unsigned long long pack2(float lo, float hi) {
    unsigned long long r;
    asm("mov.b64 %0, {%1, %2};" : "=l"(r) : "f"(lo), "f"(hi));
    return r;
}
__device__ __forceinline__ unsigned long long fma2(unsigned long long a,
                                                   unsigned long long b,
                                                   unsigned long long c) {
    unsigned long long d;
    asm("fma.rn.f32x2 %0, %1, %2, %3;" : "=l"(d) : "l"(a), "l"(b), "l"(c));
    return d;
}
__device__ __forceinline__ void unpack2(unsigned long long v, float& lo, float& hi) {
    asm("mov.b64 {%0, %1}, %2;" : "=f"(lo), "=f"(hi) : "l"(v));
}

__global__ __launch_bounds__(TPB)
void lightwin_kernel(const float2* __restrict__ x, const int* __restrict__ buckets,
                     const float* __restrict__ W1, const float* __restrict__ b1,
                     float* __restrict__ out, int B) {
    __shared__ __align__(16) float sAB[HID * 2];  // A = W1 row0, B = W1 row1
    __shared__ __align__(16) float sC[HID];       // b1
    __shared__ float sV[NB * VST];
    __shared__ float sc[NB];

    int tid = threadIdx.x;
    for (int i = tid; i < NB * VST; i += TPB) sV[i] = g_V[i];
    if (tid < NB)      sc[tid]  = g_c[tid];
    if (tid < HID * 2) sAB[tid] = W1[tid];
    if (tid < HID)     sC[tid]  = b1[tid];
    __syncthreads();

    int base = blockIdx.x * (TPB * RPT) + tid;

    unsigned long long x0d[RPT], x1d[RPT];
    float acc0[RPT], acc1[RPT];
    int   vb[RPT];

    #pragma unroll
    for (int r = 0; r < RPT; r++) {
        int idx = base + r * TPB;
        bool p = idx < B;
        float2 xv = p ? __ldg(&x[idx]) : make_float2(0.f, 0.f);
        int b = p ? buckets[idx] : 0;
        b = ((unsigned)b < NB) ? b : (NB - 1);
        vb[r]  = b * VST;
        x0d[r] = pack2(xv.x, xv.x);
        x1d[r] = pack2(xv.y, xv.y);
        acc0[r] = sc[b];     // fold head bias into accumulator
        acc1[r] = 0.f;
    }

    #pragma unroll
    for (int jj = 0; jj < JJ; jj++) {
        // uniform weight pairs: broadcast LDS.64 (naturally contiguous, no dup needed)
        unsigned long long a2  = *(const unsigned long long*)&sAB[2 * jj];
        unsigned long long b2w = *(const unsigned long long*)&sAB[HID + 2 * jj];
        unsigned long long c2  = *(const unsigned long long*)&sC[2 * jj];
        #pragma unroll
        for (int r = 0; r < RPT; r++) {
            unsigned long long z = fma2(x1d[r], b2w, c2);
            z = fma2(x0d[r], a2, z);
            float z0, z1;
            unpack2(z, z0, z1);
            float h0 = fmaxf(z0, 0.f);
            float h1 = fmaxf(z1, 0.f);
            float v0 = sV[vb[r] + 2 * jj];      // stride-33: bank = (b + j) mod 32
            float v1 = sV[vb[r] + 2 * jj + 1];
            acc0[r] = fmaf(h0, v0, acc0[r]);
            acc1[r] = fmaf(h1, v1, acc1[r]);
        }
    }

    #pragma unroll
    for (int r = 0; r < RPT; r++) {
        int idx = base + r * TPB;
        if (idx < B) out[idx] = acc0[r] + acc1[r];
    }
}

extern "C" void kernel_launch(void* const* d_in, const int* in_sizes, int n_in,
                              void* d_out, int out_size) {
    const float2* x     = (const float2*)d_in[0];
    const int* buckets  = (const int*)d_in[1];
    const float* W1     = (const float*)d_in[2];
    const float* b1     = (const float*)d_in[3];
    const float* W2     = (const float*)d_in[4];
    const float* b2     = (const float*)d_in[5];
    const float* Wh     = (const float*)d_in[6];
    const float* bh     = (const float*)d_in[7];
    float* out          = (float*)d_out;

    int B = in_sizes[1];  // buckets element count = row count

    precompute_kernel<<<8, 256>>>(W2, b2, Wh, bh);

    int rows_per_block = TPB * RPT;
    int grid = (B + rows_per_block - 1) / rows_per_block;
    lightwin_kernel<<<grid, TPB>>>(x, buckets, W1, b1, out, B);
}

// round 2
// speedup vs baseline: 1.1664x; 1.1664x over previous
#include <cuda_runtime.h>
#include <cuda_fp16.h>

#define NB    50
#define HID   32
#define HALFD 16
#define JJ    16         // HID/2 packed pairs
#define VSTH  17         // u32 stride per bucket row (16 half2 + 1 pad -> odd: <=2-way conflicts)
#define TPB   256
#define RPT   8          // rows per thread

// Precomputed combined head weights (scratch: __device__ globals, no alloc)
__device__ unsigned g_Vh[NB * VSTH];   // V = Wh @ W2^T, stored as half2 pairs
__device__ float    g_c[NB];           // c[b] = bh[b] + b2 . Wh[b]

__global__ void precompute_kernel(const float* __restrict__ W2, const float* __restrict__ b2,
                                  const float* __restrict__ Wh, const float* __restrict__ bh) {
    int t  = blockIdx.x * blockDim.x + threadIdx.x;
    int nt = gridDim.x * blockDim.x;
    // V[b][j] = sum_k W2[j][k] * Wh[b][k]; store pairs (2jj, 2jj+1) as half2
    for (int e = t; e < NB * JJ; e += nt) {
        int b = e / JJ, jj = e % JJ;
        float s0 = 0.f, s1 = 0.f;
        #pragma unroll
        for (int k = 0; k < HALFD; k++) {
            float wh = Wh[b * HALFD + k];
            s0 = fmaf(W2[(2 * jj)     * HALFD + k], wh, s0);
            s1 = fmaf(W2[(2 * jj + 1) * HALFD + k], wh, s1);
        }
        __half2 h = __floats2half2_rn(s0, s1);
        g_Vh[b * VSTH + jj] = *reinterpret_cast<unsigned*>(&h);
    }
    // c[b] = bh[b] + sum_k b2[k] * Wh[b][k]
    for (int b = t; b < NB; b += nt) {
        float s = bh[b];
        #pragma unroll
        for (int k = 0; k < HALFD; k++)
            s = fmaf(b2[k], Wh[b * HALFD + k], s);
        g_c[b] = s;
    }
}

__device__ __forceinline__ unsigned long long pack2(float lo, float hi) {
    unsigned long long r;
    asm("mov.b64 %0, {%1, %2};" : "=l"(r) : "f"(lo), "f"(hi));
    return r;
}
__device__ __forceinline__ unsigned long long fma2(unsigned long long a,
                                                   unsigned long long b,
                                                   unsigned long long c) {
    unsigned long long d;
    asm("fma.rn.f32x2 %0, %1, %2, %3;" : "=l"(d) : "l"(a), "l"(b), "l"(c));
    return d;
}
__device__ __forceinline__ void unpack2(unsigned long long v, float& lo, float& hi) {
    asm("mov.b64 {%0, %1}, %2;" : "=f"(lo), "=f"(hi) : "l"(v));
}

__global__ __launch_bounds__(TPB)
void lightwin_kernel(const float2* __restrict__ x, const int* __restrict__ buckets,
                     const float* __restrict__ W1, const float* __restrict__ b1,
                     float* __restrict__ out, int B) {
    __shared__ __align__(16) float sAB[HID * 2];   // A = W1 row0, B = W1 row1
    __shared__ __align__(16) float sC[HID];        // b1
    __shared__ unsigned sVh[NB * VSTH];            // half2 pairs, stride 17 u32
    __shared__ float sc[NB];

    int tid = threadIdx.x;
    for (int i = tid; i < NB * VSTH; i += TPB) sVh[i] = g_Vh[i];
    if (tid < NB)      sc[tid]  = g_c[tid];
    if (tid < HID * 2) sAB[tid] = W1[tid];
    if (tid < HID)     sC[tid]  = b1[tid];
    __syncthreads();

    int base = blockIdx.x * (TPB * RPT) + tid;

    unsigned long long x0d[RPT], x1d[RPT];
    float acc0[RPT], acc1[RPT];
    int   va[RPT];

    #pragma unroll
    for (int r = 0; r < RPT; r++) {
        int idx = base + r * TPB;
        bool p = idx < B;
        float2 xv = p ? __ldg(&x[idx]) : make_float2(0.f, 0.f);
        int b = p ? buckets[idx] : 0;
        b = ((unsigned)b < NB) ? b : (NB - 1);
        va[r]   = b * VSTH;
        x0d[r]  = pack2(xv.x, xv.x);
        x1d[r]  = pack2(xv.y, xv.y);
        acc0[r] = sc[b];            // fold head bias into accumulator
        acc1[r] = 0.f;
    }

    #pragma unroll
    for (int jj = 0; jj < JJ; jj++) {
        // uniform weight pairs: broadcast LDS.64 (all lanes same address -> 1 wavefront)
        unsigned long long a2  = *(const unsigned long long*)&sAB[2 * jj];
        unsigned long long b2w = *(const unsigned long long*)&sAB[HID + 2 * jj];
        unsigned long long c2  = *(const unsigned long long*)&sC[2 * jj];
        #pragma unroll
        for (int r = 0; r < RPT; r++) {
            unsigned long long z = fma2(x1d[r], b2w, c2);
            z = fma2(x0d[r], a2, z);
            float z0, z1;
            unpack2(z, z0, z1);
            float h0 = fmaxf(z0, 0.f);
            float h1 = fmaxf(z1, 0.f);
            unsigned vh = sVh[va[r] + jj];          // one LDS.32 = both weights
            float2 vf = __half22float2(*reinterpret_cast<__half2*>(&vh));
            acc0[r] = fmaf(h0, vf.x, acc0[r]);
            acc1[r] = fmaf(h1, vf.y, acc1[r]);
        }
    }

    #pragma unroll
    for (int r = 0; r < RPT; r++) {
        int idx = base + r * TPB;
        if (idx < B) out[idx] = acc0[r] + acc1[r];
    }
}

extern "C" void kernel_launch(void* const* d_in, const int* in_sizes, int n_in,
                              void* d_out, int out_size) {
    const float2* x     = (const float2*)d_in[0];
    const int* buckets  = (const int*)d_in[1];
    const float* W1     = (const float*)d_in[2];
    const float* b1     = (const float*)d_in[3];
    const float* W2     = (const float*)d_in[4];
    const float* b2     = (const float*)d_in[5];
    const float* Wh     = (const float*)d_in[6];
    const float* bh     = (const float*)d_in[7];
    float* out          = (float*)d_out;

    int B = in_sizes[1];  // buckets element count = row count

    precompute_kernel<<<8, 256>>>(W2, b2, Wh, bh);

    int rows_per_block = TPB * RPT;
    int grid = (B + rows_per_block - 1) / rows_per_block;
    lightwin_kernel<<<grid, TPB>>>(x, buckets, W1, b1, out, B);
}